// round 16
// baseline (speedup 1.0000x reference)
#include <cuda_runtime.h>
#include <math.h>
#include <stdint.h>

#define NB    16
#define C     384
#define C3    1152
#define HIN   64
#define HH    16
#define L     256
#define HEADS 12
#define HD    32
#define EPS   1e-5f
#define KPAD  36
#define ASTG  4608

// ---------------- scratch (device globals) ---------------------------------
__device__ float g_xd  [NB * C  * L];
__device__ float g_xd2 [NB * C  * L];
__device__ float g_qkv [NB * C3 * L];
__device__ float g_att [NB * C  * C];
__device__ float g_vals[NB * C  * L];
__device__ float g_stats1[NB * C * 2];      // per-(n,c) partials from dwconv
__device__ float g_stats2[NB * 12 * 2];     // per-(n,tile) partials from out-proj GEMM
// GN-folded weights + row vectors
__device__ float g_Wf1 [C3 * C];
__device__ float g_Wf2 [C3 * C];
__device__ float g_wb1 [C3];
__device__ float g_wg1 [C3];
__device__ float g_wb2 [C3];
__device__ float g_wg2 [C3];

__device__ __forceinline__ float warpsum(float v) {
    #pragma unroll
    for (int o = 16; o; o >>= 1) v += __shfl_down_sync(0xffffffffu, v, o);
    return v;
}

// ---------------- depthwise 7x7 stride-4 conv + BN + GN partial stats ------
__global__ void __launch_bounds__(256) k_dwconv(
    const float* __restrict__ x, const float* __restrict__ w,
    const float* __restrict__ bg, const float* __restrict__ bb,
    const float* __restrict__ bm, const float* __restrict__ bv)
{
    __shared__ float sx[HIN][72];
    __shared__ float sw[49];
    __shared__ float ra[8], rb[8];
    int n = blockIdx.x / C, c = blockIdx.x % C;
    const float4* xp4 = (const float4*)(x + ((size_t)n * C + c) * (HIN * HIN));
    #pragma unroll
    for (int k = 0; k < 4; k++) {
        int i = threadIdx.x + k * 256;
        int row = i >> 4, c4 = i & 15;
        *(float4*)&sx[row][4 + 4 * c4] = xp4[i];
    }
    if (threadIdx.x < 128) {
        int row = threadIdx.x >> 1, side = threadIdx.x & 1;
        *(float4*)&sx[row][side ? 68 : 0] = make_float4(0.f, 0.f, 0.f, 0.f);
    }
    if (threadIdx.x < 49) sw[threadIdx.x] = w[c * 49 + threadIdx.x];
    __syncthreads();

    float scale = bg[c] * rsqrtf(bv[c] + EPS);
    float bias  = bb[c] - bm[c] * scale;

    int oy = threadIdx.x >> 4, ox = threadIdx.x & 15;
    int iy0 = oy * 4 - 3;
    float acc = 0.f;
    #pragma unroll
    for (int ky = 0; ky < 7; ky++) {
        int iy = iy0 + ky;
        if ((unsigned)iy < (unsigned)HIN) {
            const float4* r = (const float4*)&sx[iy][4 * ox];
            float4 a = r[0], b2 = r[1];
            float v[8] = {a.x, a.y, a.z, a.w, b2.x, b2.y, b2.z, b2.w};
            const float* wr = &sw[ky * 7];
            #pragma unroll
            for (int kx = 0; kx < 7; kx++)
                acc += v[kx + 1] * wr[kx];
        }
    }
    float out = acc * scale + bias;
    g_xd[((size_t)n * C + c) * L + threadIdx.x] = out;

    float s = warpsum(out), s2 = warpsum(out * out);
    int w8 = threadIdx.x >> 5, ln = threadIdx.x & 31;
    if (ln == 0) { ra[w8] = s; rb[w8] = s2; }
    __syncthreads();
    if (threadIdx.x == 0) {
        s  = ra[0] + ra[1] + ra[2] + ra[3] + ra[4] + ra[5] + ra[6] + ra[7];
        s2 = rb[0] + rb[1] + rb[2] + rb[3] + rb[4] + rb[5] + rb[6] + rb[7];
        g_stats1[(n * C + c) * 2]     = s;
        g_stats1[(n * C + c) * 2 + 1] = s2;
    }
}

// ---------------- GN weight folding (both sets in one launch) ---------------
__global__ void __launch_bounds__(128) k_fold2(
    const float* __restrict__ W1, const float* __restrict__ g1c, const float* __restrict__ b1c,
    const float* __restrict__ W2, const float* __restrict__ g2c, const float* __restrict__ b2c)
{
    int id = blockIdx.x, t = threadIdx.x;
    int set = id >= C3;
    int m = set ? id - C3 : id;
    const float* W     = set ? W2 : W1;
    const float* gamma = set ? g2c : g1c;
    const float* beta  = set ? b2c : b1c;
    float* Wf = set ? g_Wf2 : g_Wf1;
    float* wb = set ? g_wb2 : g_wb1;
    float* wg = set ? g_wg2 : g_wg1;

    float sb = 0.f, sg = 0.f;
    for (int c = t; c < C; c += 128) {
        float wv = W[m * C + c];
        float gv = wv * gamma[c];
        Wf[m * C + c] = gv;
        sb += wv * beta[c];
        sg += gv;
    }
    __shared__ float a[4], g2[4];
    sb = warpsum(sb); sg = warpsum(sg);
    if ((t & 31) == 0) { a[t >> 5] = sb; g2[t >> 5] = sg; }
    __syncthreads();
    if (t == 0) {
        wb[m] = a[0] + a[1] + a[2] + a[3];
        wg[m] = g2[0] + g2[1] + g2[2] + g2[3];
    }
}

// ---------------- tf32 mma + cp.async helpers ------------------------------
__device__ __forceinline__ void mma_tf32(float c[4], const uint32_t a[4], const uint32_t b[2]) {
    asm volatile(
        "mma.sync.aligned.m16n8k8.row.col.f32.tf32.tf32.f32 "
        "{%0,%1,%2,%3}, {%4,%5,%6,%7}, {%8,%9}, {%0,%1,%2,%3};"
        : "+f"(c[0]), "+f"(c[1]), "+f"(c[2]), "+f"(c[3])
        : "r"(a[0]), "r"(a[1]), "r"(a[2]), "r"(a[3]), "r"(b[0]), "r"(b[1]));
}
__device__ __forceinline__ void cpa16(uint32_t s, const float* g) {
    asm volatile("cp.async.cg.shared.global [%0], [%1], 16;" :: "r"(s), "l"(g));
}

// ---------------- tf32 tensor-core GEMM, BK=32, 3-stage, BM=128, BN=128|64 --
// EPI=0: C = alpha*acc
// EPI=1: C = acc + R[b] + bias[row]
// EPI=3: EPI=1 + write tile (sum,sumsq) to part[(b*nblk+blk)*2]
// EPI=2: GN fold; mean/istd from part; C = istd*acc + (bias[row] - mean*istd*R[row])
template<int TRANSB, int EPI, int BN>
__global__ void __launch_bounds__(256) k_gemm_tc(
    const float* __restrict__ A, const float* __restrict__ B, float* __restrict__ Cm,
    int K, int lda, int ldb, int ldc,
    long sA, long sB, long sC,
    float alpha, const float* __restrict__ R, long sR, const float* __restrict__ bias,
    float* __restrict__ part, int npart)
{
    constexpr int MI      = (BN == 128) ? 4 : 2;
    constexpr int BSTG    = (BN == 128) ? 4608 : 2304;     // floats per B stage
    constexpr int BSTRIDE = (BN == 128) ? 136 : 72;        // nontrans B row stride

    extern __shared__ float smem[];
    int b = blockIdx.z;
    const float* Ab = A + (size_t)b * sA;
    const float* Bb = B + (size_t)b * sB;
    int t = threadIdx.x;
    int rowBase = blockIdx.y * 128, colBase = blockIdx.x * BN;

    int ar = t >> 3, ac = (t & 7) << 2;        // 32 rows x 32 k per pass

    uint32_t asB = (uint32_t)__cvta_generic_to_shared(smem);
    uint32_t buB = (uint32_t)__cvta_generic_to_shared(smem + 3 * ASTG);

    auto loadStage = [&](int k0, int st) {
        #pragma unroll
        for (int r = 0; r < 4; r++) {
            int row = ar + r * 32;
            cpa16(asB + (uint32_t)(st * ASTG + row * KPAD + ac) * 4,
                  Ab + (size_t)(rowBase + row) * lda + k0 + ac);
        }
        if (TRANSB) {
            #pragma unroll
            for (int r = 0; r < BN / 32; r++) {
                int row = ar + r * 32;
                cpa16(buB + (uint32_t)(st * BSTG + row * KPAD + ac) * 4,
                      Bb + (size_t)(colBase + row) * ldb + k0 + ac);
            }
        } else if (BN == 128) {
            int bk = t >> 5, bc = (t & 31) << 2;
            #pragma unroll
            for (int r = 0; r < 4; r++) {
                int k = bk + r * 8;
                cpa16(buB + (uint32_t)(st * BSTG + k * BSTRIDE + bc) * 4,
                      Bb + (size_t)(k0 + k) * ldb + colBase + bc);
            }
        } else {
            int bk = t >> 4, bc = (t & 15) << 2;
            #pragma unroll
            for (int r = 0; r < 2; r++) {
                int k = bk + r * 16;
                cpa16(buB + (uint32_t)(st * BSTG + k * BSTRIDE + bc) * 4,
                      Bb + (size_t)(k0 + k) * ldb + colBase + bc);
            }
        }
    };

    int nIter = K >> 5;
    loadStage(0, 0);
    asm volatile("cp.async.commit_group;");
    loadStage(32, 1);
    asm volatile("cp.async.commit_group;");

    int lane = t & 31, w = t >> 5;
    int wm = (BN == 128) ? (w >> 2) * 64 : (w >> 1) * 32;
    int wn = (BN == 128) ? (w & 3) * 32 : (w & 1) * 32;
    int lk = lane & 3, lm = lane >> 2;
    float acc[MI][4][4] = {};

    int cur = 0;
    for (int it = 0; it < nIter; ++it) {
        if (it + 2 < nIter) { asm volatile("cp.async.wait_group 1;"); }
        else               { asm volatile("cp.async.wait_group 0;"); }
        __syncthreads();
        if (it + 2 < nIter) {
            int st = cur - 1; if (st < 0) st += 3;
            loadStage((it + 2) << 5, st);
            asm volatile("cp.async.commit_group;");
        }
        const float* Asc = smem + cur * ASTG;
        const float* Bsc = smem + 3 * ASTG + cur * BSTG;
        #pragma unroll
        for (int kk = 0; kk < 32; kk += 8) {
            uint32_t af[MI][4], bf[4][2];
            #pragma unroll
            for (int mi = 0; mi < MI; mi++) {
                int row = wm + mi * 16 + lm;
                af[mi][0] = __float_as_uint(Asc[row * KPAD + kk + lk]);
                af[mi][1] = __float_as_uint(Asc[(row + 8) * KPAD + kk + lk]);
                af[mi][2] = __float_as_uint(Asc[row * KPAD + kk + 4 + lk]);
                af[mi][3] = __float_as_uint(Asc[(row + 8) * KPAD + kk + 4 + lk]);
            }
            #pragma unroll
            for (int ni = 0; ni < 4; ni++) {
                int col = wn + ni * 8 + lm;
                if (TRANSB) {
                    bf[ni][0] = __float_as_uint(Bsc[col * KPAD + kk + lk]);
                    bf[ni][1] = __float_as_uint(Bsc[col * KPAD + kk + 4 + lk]);
                } else {
                    bf[ni][0] = __float_as_uint(Bsc[(kk + lk) * BSTRIDE + col]);
                    bf[ni][1] = __float_as_uint(Bsc[(kk + 4 + lk) * BSTRIDE + col]);
                }
            }
            #pragma unroll
            for (int mi = 0; mi < MI; mi++)
                #pragma unroll
                for (int ni = 0; ni < 4; ni++)
                    mma_tf32(acc[mi][ni], af[mi], bf[ni]);
        }
        cur++; if (cur == 3) cur = 0;
    }

    float* Cb = Cm + (size_t)b * sC;
    const float* Rb = (EPI == 1 || EPI == 3) ? (R + (size_t)b * sR) : R;
    float mean = 0.f, istd = 1.f;
    if (EPI == 2) {
        __syncthreads();
        if (t < 32) {
            float s = 0.f, s2 = 0.f;
            for (int i = t; i < npart; i += 32) {
                s  += part[(b * npart + i) * 2];
                s2 += part[(b * npart + i) * 2 + 1];
            }
            s = warpsum(s); s2 = warpsum(s2);
            if (t == 0) { smem[0] = s; smem[1] = s2; }
        }
        __syncthreads();
        float invN = 1.f / (C * L);
        mean = smem[0] * invN;
        istd = rsqrtf(smem[1] * invN - mean * mean + EPS);
    }
    float ls = 0.f, ls2 = 0.f;
    #pragma unroll
    for (int mi = 0; mi < MI; mi++) {
        #pragma unroll
        for (int ni = 0; ni < 4; ni++) {
            int r0 = rowBase + wm + mi * 16 + lm;
            int cc = colBase + wn + ni * 8 + 2 * lk;
            if (EPI == 1 || EPI == 3) {
                float bv0 = bias[r0], bv1 = bias[r0 + 8];
                float2 rv0 = *(const float2*)(Rb + (size_t)r0 * ldc + cc);
                float2 rv1 = *(const float2*)(Rb + (size_t)(r0 + 8) * ldc + cc);
                float o0 = acc[mi][ni][0] + rv0.x + bv0;
                float o1 = acc[mi][ni][1] + rv0.y + bv0;
                float o2 = acc[mi][ni][2] + rv1.x + bv1;
                float o3 = acc[mi][ni][3] + rv1.y + bv1;
                *(float2*)(Cb + (size_t)r0 * ldc + cc)       = make_float2(o0, o1);
                *(float2*)(Cb + (size_t)(r0 + 8) * ldc + cc) = make_float2(o2, o3);
                if (EPI == 3) {
                    ls  += o0 + o1 + o2 + o3;
                    ls2 += o0 * o0 + o1 * o1 + o2 * o2 + o3 * o3;
                }
            } else if (EPI == 2) {
                float rb0 = bias[r0]     - mean * istd * Rb[r0];
                float rb1 = bias[r0 + 8] - mean * istd * Rb[r0 + 8];
                *(float2*)(Cb + (size_t)r0 * ldc + cc) =
                    make_float2(acc[mi][ni][0] * istd + rb0, acc[mi][ni][1] * istd + rb0);
                *(float2*)(Cb + (size_t)(r0 + 8) * ldc + cc) =
                    make_float2(acc[mi][ni][2] * istd + rb1, acc[mi][ni][3] * istd + rb1);
            } else {
                *(float2*)(Cb + (size_t)r0 * ldc + cc) =
                    make_float2(acc[mi][ni][0] * alpha, acc[mi][ni][1] * alpha);
                *(float2*)(Cb + (size_t)(r0 + 8) * ldc + cc) =
                    make_float2(acc[mi][ni][2] * alpha, acc[mi][ni][3] * alpha);
            }
        }
    }
    if (EPI == 3) {
        __syncthreads();
        ls = warpsum(ls); ls2 = warpsum(ls2);
        if (lane == 0) { smem[w * 2] = ls; smem[w * 2 + 1] = ls2; }
        __syncthreads();
        if (t == 0) {
            float s = 0.f, s2 = 0.f;
            #pragma unroll
            for (int i = 0; i < 8; i++) { s += smem[i * 2]; s2 += smem[i * 2 + 1]; }
            int nblk = gridDim.x * gridDim.y;
            int p = blockIdx.y * gridDim.x + blockIdx.x;
            part[(b * nblk + p) * 2]     = s;
            part[(b * nblk + p) * 2 + 1] = s2;
        }
    }
}

// ---------------- channel-attention softmax (rows of 384) ------------------
__global__ void __launch_bounds__(128) k_softmax(float* __restrict__ att) {
    float* p = att + (size_t)blockIdx.x * C;
    float v0 = p[threadIdx.x], v1 = p[threadIdx.x + 128], v2 = p[threadIdx.x + 256];
    float mx = fmaxf(v0, fmaxf(v1, v2));
    __shared__ float sh[4], sh2[4];
    #pragma unroll
    for (int o = 16; o; o >>= 1) mx = fmaxf(mx, __shfl_xor_sync(0xffffffffu, mx, o));
    if ((threadIdx.x & 31) == 0) sh[threadIdx.x >> 5] = mx;
    __syncthreads();
    mx = fmaxf(fmaxf(sh[0], sh[1]), fmaxf(sh[2], sh[3]));
    v0 = __expf(v0 - mx); v1 = __expf(v1 - mx); v2 = __expf(v2 - mx);
    float s = v0 + v1 + v2;
    #pragma unroll
    for (int o = 16; o; o >>= 1) s += __shfl_xor_sync(0xffffffffu, s, o);
    if ((threadIdx.x & 31) == 0) sh2[threadIdx.x >> 5] = s;
    __syncthreads();
    s = sh2[0] + sh2[1] + sh2[2] + sh2[3];
    float inv = 1.f / s;
    p[threadIdx.x] = v0 * inv; p[threadIdx.x + 128] = v1 * inv; p[threadIdx.x + 256] = v2 * inv;
}

// ---------------- spatial attention: flash-style tf32 MMA ------------------
__global__ void __launch_bounds__(256) k_spattn_mma() {
    extern __shared__ float sh[];
    float* KT  = sh;
    float* VT  = sh + 256 * KPAD;
    float* Psm = sh + 2 * 256 * KPAD;
    int n = blockIdx.x / HEADS, h = blockIdx.x % HEADS;
    const float* base = g_qkv + (size_t)n * C3 * L + (size_t)h * (3 * HD) * L;
    int t = threadIdx.x, lane = t & 31, w = t >> 5;

    for (int i = t; i < HD * L; i += 256) {
        int d = i >> 8, l = i & 255;
        KT[l * KPAD + d] = base[(HD + d) * L + l];
        VT[l * KPAD + d] = base[(2 * HD + d) * L + l];
    }

    int lm = lane >> 2, lk = lane & 3;
    int qb = w * 32;
    const float scl = 0.17677669529663689f;
    uint32_t qf[2][4][4];
    #pragma unroll
    for (int mi = 0; mi < 2; mi++) {
        int r0 = qb + mi * 16 + lm;
        #pragma unroll
        for (int ks = 0; ks < 4; ks++) {
            int k0 = ks * 8;
            qf[mi][ks][0] = __float_as_uint(base[(k0 + lk) * L + r0]     * scl);
            qf[mi][ks][1] = __float_as_uint(base[(k0 + lk) * L + r0 + 8] * scl);
            qf[mi][ks][2] = __float_as_uint(base[(k0 + 4 + lk) * L + r0]     * scl);
            qf[mi][ks][3] = __float_as_uint(base[(k0 + 4 + lk) * L + r0 + 8] * scl);
        }
    }
    __syncthreads();

    float* Pw = Psm + w * 32 * KPAD;
    float m[4], lsum[4];
    #pragma unroll
    for (int i = 0; i < 4; i++) { m[i] = -1e30f; lsum[i] = 0.f; }
    float oacc[2][4][4] = {};

    for (int c0 = 0; c0 < L; c0 += 32) {
        float sacc[2][4][4] = {};
        #pragma unroll
        for (int ks = 0; ks < 4; ks++) {
            int kk = ks * 8;
            uint32_t bf[4][2];
            #pragma unroll
            for (int ni = 0; ni < 4; ni++) {
                int col = c0 + ni * 8 + lm;
                bf[ni][0] = __float_as_uint(KT[col * KPAD + kk + lk]);
                bf[ni][1] = __float_as_uint(KT[col * KPAD + kk + 4 + lk]);
            }
            #pragma unroll
            for (int mi = 0; mi < 2; mi++)
                #pragma unroll
                for (int ni = 0; ni < 4; ni++)
                    mma_tf32(sacc[mi][ni], qf[mi][ks], bf[ni]);
        }
        #pragma unroll
        for (int mi = 0; mi < 2; mi++) {
            float cm0 = -1e30f, cm1 = -1e30f;
            #pragma unroll
            for (int ni = 0; ni < 4; ni++) {
                cm0 = fmaxf(cm0, fmaxf(sacc[mi][ni][0], sacc[mi][ni][1]));
                cm1 = fmaxf(cm1, fmaxf(sacc[mi][ni][2], sacc[mi][ni][3]));
            }
            cm0 = fmaxf(cm0, __shfl_xor_sync(0xffffffffu, cm0, 1));
            cm0 = fmaxf(cm0, __shfl_xor_sync(0xffffffffu, cm0, 2));
            cm1 = fmaxf(cm1, __shfl_xor_sync(0xffffffffu, cm1, 1));
            cm1 = fmaxf(cm1, __shfl_xor_sync(0xffffffffu, cm1, 2));
            float nm0 = fmaxf(m[2 * mi],     cm0);
            float nm1 = fmaxf(m[2 * mi + 1], cm1);
            float f0 = __expf(m[2 * mi] - nm0);
            float f1 = __expf(m[2 * mi + 1] - nm1);
            float ps0 = 0.f, ps1 = 0.f;
            int rA = (mi * 16 + lm) * KPAD, rB = (mi * 16 + lm + 8) * KPAD;
            #pragma unroll
            for (int ni = 0; ni < 4; ni++) {
                float p0 = __expf(sacc[mi][ni][0] - nm0);
                float p1 = __expf(sacc[mi][ni][1] - nm0);
                float p2 = __expf(sacc[mi][ni][2] - nm1);
                float p3 = __expf(sacc[mi][ni][3] - nm1);
                ps0 += p0 + p1; ps1 += p2 + p3;
                int col = ni * 8 + 2 * lk;
                Pw[rA + col] = p0; Pw[rA + col + 1] = p1;
                Pw[rB + col] = p2; Pw[rB + col + 1] = p3;
            }
            ps0 += __shfl_xor_sync(0xffffffffu, ps0, 1);
            ps0 += __shfl_xor_sync(0xffffffffu, ps0, 2);
            ps1 += __shfl_xor_sync(0xffffffffu, ps1, 1);
            ps1 += __shfl_xor_sync(0xffffffffu, ps1, 2);
            lsum[2 * mi]     = lsum[2 * mi]     * f0 + ps0;
            lsum[2 * mi + 1] = lsum[2 * mi + 1] * f1 + ps1;
            #pragma unroll
            for (int ni = 0; ni < 4; ni++) {
                oacc[mi][ni][0] *= f0; oacc[mi][ni][1] *= f0;
                oacc[mi][ni][2] *= f1; oacc[mi][ni][3] *= f1;
            }
            m[2 * mi] = nm0; m[2 * mi + 1] = nm1;
        }
        __syncwarp();
        #pragma unroll
        for (int ks = 0; ks < 4; ks++) {
            int kk = ks * 8;
            uint32_t af[2][4], bf[4][2];
            #pragma unroll
            for (int mi = 0; mi < 2; mi++) {
                int row = mi * 16 + lm;
                af[mi][0] = __float_as_uint(Pw[row * KPAD + kk + lk]);
                af[mi][1] = __float_as_uint(Pw[(row + 8) * KPAD + kk + lk]);
                af[mi][2] = __float_as_uint(Pw[row * KPAD + kk + 4 + lk]);
                af[mi][3] = __float_as_uint(Pw[(row + 8) * KPAD + kk + 4 + lk]);
            }
            #pragma unroll
            for (int ni = 0; ni < 4; ni++) {
                int dcol = ni * 8 + lm;
                bf[ni][0] = __float_as_uint(VT[(c0 + kk + lk) * KPAD + dcol]);
                bf[ni][1] = __float_as_uint(VT[(c0 + kk + 4 + lk) * KPAD + dcol]);
            }
            #pragma unroll
            for (int mi = 0; mi < 2; mi++)
                #pragma unroll
                for (int ni = 0; ni < 4; ni++)
                    mma_tf32(oacc[mi][ni], af[mi], bf[ni]);
        }
        __syncwarp();
    }

    float inv[4];
    #pragma unroll
    for (int i = 0; i < 4; i++) inv[i] = 1.f / lsum[i];
    float* outp = g_vals + (size_t)n * C * L + (size_t)h * HD * L;
    #pragma unroll
    for (int mi = 0; mi < 2; mi++) {
        int r0 = qb + mi * 16 + lm;
        #pragma unroll
        for (int ni = 0; ni < 4; ni++) {
            int cc = ni * 8 + 2 * lk;
            outp[cc * L + r0]           = oacc[mi][ni][0] * inv[2 * mi];
            outp[(cc + 1) * L + r0]     = oacc[mi][ni][1] * inv[2 * mi];
            outp[cc * L + r0 + 8]       = oacc[mi][ni][2] * inv[2 * mi + 1];
            outp[(cc + 1) * L + r0 + 8] = oacc[mi][ni][3] * inv[2 * mi + 1];
        }
    }
}

// ---------------- depthwise convtranspose (k=8,s=4,p=2) + residual ---------
__global__ void __launch_bounds__(256) k_up(
    const float* __restrict__ x, const float* __restrict__ w,
    const float* __restrict__ ub, float* __restrict__ out)
{
    int idx = blockIdx.x * 256 + threadIdx.x;
    int xb = idx & 15;
    int yq = (idx >> 4) & 63;
    int c  = (idx >> 10) % C;
    int n  = idx / (1024 * C);
    const float* xdp = g_xd + ((size_t)n * C + c) * L;
    const float* wp  = w + c * 64;
    int iy1 = (yq + 2) >> 2;
    float res[4] = {0.f, 0.f, 0.f, 0.f};
    #pragma unroll
    for (int a = 0; a < 2; a++) {
        int iy = iy1 - a, ky = yq + 2 - 4 * iy;
        if ((unsigned)iy < 16u && (unsigned)ky < 8u) {
            const float* xr = xdp + iy * HH;
            float xm1 = (xb > 0)  ? xr[xb - 1] : 0.f;
            float x0  = xr[xb];
            float xp1 = (xb < 15) ? xr[xb + 1] : 0.f;
            const float* wr = wp + ky * 8;
            res[0] += x0 * wr[2];
            if (xb > 0)  res[0] += xm1 * wr[6];
            res[1] += x0 * wr[3];
            if (xb > 0)  res[1] += xm1 * wr[7];
            res[2] += x0 * wr[4];
            if (xb < 15) res[2] += xp1 * wr[0];
            res[3] += x0 * wr[5];
            if (xb < 15) res[3] += xp1 * wr[1];
        }
    }
    float4 xv = ((const float4*)x)[idx];
    float ubc = ub[c];
    ((float4*)out)[idx] = make_float4(xv.x + res[0] + ubc, xv.y + res[1] + ubc,
                                      xv.z + res[2] + ubc, xv.w + res[3] + ubc);
}

// ---------------- host launcher -------------------------------------------
#define SMEM128 ((3 * ASTG + 3 * 4608) * 4)   // 110592 bytes
#define SMEM64  ((3 * ASTG + 3 * 2304) * 4)   // 82944 bytes
#define SPATTN_SMEM ((2 * 256 * KPAD + 8 * 32 * KPAD) * 4)

extern "C" void kernel_launch(void* const* d_in, const int* in_sizes, int n_in,
                              void* d_out, int out_size)
{
    const float* x        = (const float*)d_in[0];
    const float* dw_w     = (const float*)d_in[1];
    const float* bn_gamma = (const float*)d_in[2];
    const float* bn_beta  = (const float*)d_in[3];
    const float* bn_mean  = (const float*)d_in[4];
    const float* bn_var   = (const float*)d_in[5];
    const float* lnch_g   = (const float*)d_in[6];
    const float* lnch_b   = (const float*)d_in[7];
    const float* pw_ch    = (const float*)d_in[8];
    const float* outch_w  = (const float*)d_in[9];
    const float* outch_b  = (const float*)d_in[10];
    const float* lnsp_g   = (const float*)d_in[11];
    const float* lnsp_b   = (const float*)d_in[12];
    const float* pw_sp    = (const float*)d_in[13];
    const float* outsp_w  = (const float*)d_in[14];
    const float* outsp_b  = (const float*)d_in[15];
    const float* up_w     = (const float*)d_in[16];
    const float* up_b     = (const float*)d_in[17];
    float* out = (float*)d_out;

    float *xd, *xd2, *qkv, *att, *vals, *st1, *st2;
    float *Wf1, *Wf2, *wb1, *wg1, *wb2, *wg2;
    cudaGetSymbolAddress((void**)&xd,   g_xd);
    cudaGetSymbolAddress((void**)&xd2,  g_xd2);
    cudaGetSymbolAddress((void**)&qkv,  g_qkv);
    cudaGetSymbolAddress((void**)&att,  g_att);
    cudaGetSymbolAddress((void**)&vals, g_vals);
    cudaGetSymbolAddress((void**)&st1,  g_stats1);
    cudaGetSymbolAddress((void**)&st2,  g_stats2);
    cudaGetSymbolAddress((void**)&Wf1,  g_Wf1);
    cudaGetSymbolAddress((void**)&Wf2,  g_Wf2);
    cudaGetSymbolAddress((void**)&wb1,  g_wb1);
    cudaGetSymbolAddress((void**)&wg1,  g_wg1);
    cudaGetSymbolAddress((void**)&wb2,  g_wb2);
    cudaGetSymbolAddress((void**)&wg2,  g_wg2);

    cudaFuncSetAttribute(k_gemm_tc<0, 2, 128>, cudaFuncAttributeMaxDynamicSharedMemorySize, SMEM128);
    cudaFuncSetAttribute(k_gemm_tc<1, 0, 64>,  cudaFuncAttributeMaxDynamicSharedMemorySize, SMEM64);
    cudaFuncSetAttribute(k_gemm_tc<0, 0, 64>,  cudaFuncAttributeMaxDynamicSharedMemorySize, SMEM64);
    cudaFuncSetAttribute(k_gemm_tc<0, 3, 64>,  cudaFuncAttributeMaxDynamicSharedMemorySize, SMEM64);
    cudaFuncSetAttribute(k_gemm_tc<0, 1, 64>,  cudaFuncAttributeMaxDynamicSharedMemorySize, SMEM64);
    cudaFuncSetAttribute(k_spattn_mma, cudaFuncAttributeMaxDynamicSharedMemorySize, SPATTN_SMEM);

    // 0) fold GN affine params into projection weights
    k_fold2<<<2 * C3, 128>>>(pw_ch, lnch_g, lnch_b, pw_sp, lnsp_g, lnsp_b);

    // 1) downsample conv + BN + fused GN#1 partial stats -> g_stats1
    k_dwconv<<<NB * C, 256>>>(x, dw_w, bn_gamma, bn_beta, bn_mean, bn_var);

    // 2) qkv[n] = GN-folded QKV #1 (EPI=2, stats from g_stats1, npart=C)
    k_gemm_tc<0, 2, 128><<<dim3(L / 128, C3 / 128, NB), 256, SMEM128>>>(
        Wf1, xd, qkv, C, C, L, L,
        0, (long)C * L, (long)C3 * L, 1.f, wg1, 0, wb1, st1, C);

    // 3) scores[n] = q[n] @ k[n]^T / 16    (BN=64 -> 288 blocks)
    k_gemm_tc<1, 0, 64><<<dim3(C / 64, C / 128, NB), 256, SMEM64>>>(
        qkv, qkv + (size_t)C * L, att, L, L, L, C,
        (long)C3 * L, (long)C3 * L, (long)C * C,
        1.f / 16.f, nullptr, 0, nullptr, nullptr, 0);

    // 4) softmax rows
    k_softmax<<<NB * C, 128>>>(att);

    // 5) vals[n] = att[n] @ v[n]           (BN=64 -> 192 blocks)
    k_gemm_tc<0, 0, 64><<<dim3(L / 64, C / 128, NB), 256, SMEM64>>>(
        att, qkv + (size_t)2 * C * L, vals, C, C, L, L,
        (long)C * C, (long)C3 * L, (long)C * L,
        1.f, nullptr, 0, nullptr, nullptr, 0);

    // 6) xd2[n] = outch_w @ vals[n] + xd[n] + outch_b, + GN#2 partials (EPI=3)
    k_gemm_tc<0, 3, 64><<<dim3(L / 64, C / 128, NB), 256, SMEM64>>>(
        outch_w, vals, xd2, C, C, L, L,
        0, (long)C * L, (long)C * L,
        1.f, xd, (long)C * L, outch_b, st2, 0);

    // 7) qkv[n] = GN-folded QKV #2 (EPI=2, stats from g_stats2, npart=12)
    k_gemm_tc<0, 2, 128><<<dim3(L / 128, C3 / 128, NB), 256, SMEM128>>>(
        Wf2, xd2, qkv, C, C, L, L,
        0, (long)C * L, (long)C3 * L, 1.f, wg2, 0, wb2, st2, 12);

    // 8) fused spatial attention (tensor-core flash)
    k_spattn_mma<<<NB * HEADS, 256, SPATTN_SMEM>>>();

    // 9) xd[n] = outsp_w @ vals[n] + xd2[n] + outsp_b   (BN=64)
    k_gemm_tc<0, 1, 64><<<dim3(L / 64, C / 128, NB), 256, SMEM64>>>(
        outsp_w, vals, xd, C, C, L, L,
        0, (long)C * L, (long)C * L,
        1.f, xd2, (long)C * L, outsp_b, nullptr, 0);

    // 10) upsample transposed conv + residual
    k_up<<<(NB * C * HIN * HIN / 4) / 256, 256>>>(x, up_w, up_b, out);
}

// round 17
// speedup vs baseline: 1.0384x; 1.0384x over previous
#include <cuda_runtime.h>
#include <math.h>
#include <stdint.h>

#define NB    16
#define C     384
#define C3    1152
#define HIN   64
#define HH    16
#define L     256
#define HEADS 12
#define HD    32
#define EPS   1e-5f
#define KPAD  36

// ---------------- scratch (device globals) ---------------------------------
__device__ float g_xd  [NB * C  * L];
__device__ float g_xd2 [NB * C  * L];
__device__ float g_qkv [NB * C3 * L];
__device__ float g_att [NB * C  * C];
__device__ float g_vals[NB * C  * L];
__device__ float g_stats1[NB * C * 2];     // per-(n,c) partial sums from dwconv
__device__ float g_stats2[NB * 6 * 2];     // per-(n,tile) partial sums from out-proj GEMM
// GN-folded weights + row vectors
__device__ float g_Wf1 [C3 * C];
__device__ float g_Wf2 [C3 * C];
__device__ float g_wb1 [C3];
__device__ float g_wg1 [C3];
__device__ float g_wb2 [C3];
__device__ float g_wg2 [C3];

__device__ __forceinline__ float warpsum(float v) {
    #pragma unroll
    for (int o = 16; o; o >>= 1) v += __shfl_down_sync(0xffffffffu, v, o);
    return v;
}

// ---------------- depthwise 7x7 stride-4 conv + folded BatchNorm -----------
// + per-(n,c) GN partial stats fused into the epilogue.
__global__ void __launch_bounds__(256) k_dwconv(
    const float* __restrict__ x, const float* __restrict__ w,
    const float* __restrict__ bg, const float* __restrict__ bb,
    const float* __restrict__ bm, const float* __restrict__ bv)
{
    __shared__ float sx[HIN][72];    // [row][4 pad | 64 data | 4 pad]
    __shared__ float sw[49];
    __shared__ float ra[8], rb[8];
    int n = blockIdx.x / C, c = blockIdx.x % C;
    const float4* xp4 = (const float4*)(x + ((size_t)n * C + c) * (HIN * HIN));
    #pragma unroll
    for (int k = 0; k < 4; k++) {
        int i = threadIdx.x + k * 256;
        int row = i >> 4, c4 = i & 15;
        *(float4*)&sx[row][4 + 4 * c4] = xp4[i];
    }
    if (threadIdx.x < 128) {
        int row = threadIdx.x >> 1, side = threadIdx.x & 1;
        *(float4*)&sx[row][side ? 68 : 0] = make_float4(0.f, 0.f, 0.f, 0.f);
    }
    if (threadIdx.x < 49) sw[threadIdx.x] = w[c * 49 + threadIdx.x];
    __syncthreads();

    float scale = bg[c] * rsqrtf(bv[c] + EPS);
    float bias  = bb[c] - bm[c] * scale;

    int oy = threadIdx.x >> 4, ox = threadIdx.x & 15;
    int iy0 = oy * 4 - 3;
    float acc = 0.f;
    #pragma unroll
    for (int ky = 0; ky < 7; ky++) {
        int iy = iy0 + ky;
        if ((unsigned)iy < (unsigned)HIN) {
            const float4* r = (const float4*)&sx[iy][4 * ox];
            float4 a = r[0], b2 = r[1];
            float v[8] = {a.x, a.y, a.z, a.w, b2.x, b2.y, b2.z, b2.w};
            const float* wr = &sw[ky * 7];
            #pragma unroll
            for (int kx = 0; kx < 7; kx++)
                acc += v[kx + 1] * wr[kx];
        }
    }
    float out = acc * scale + bias;
    g_xd[((size_t)n * C + c) * L + threadIdx.x] = out;

    // fused GN partial stats for this (n,c) plane
    float s = warpsum(out), s2 = warpsum(out * out);
    int w8 = threadIdx.x >> 5, ln = threadIdx.x & 31;
    if (ln == 0) { ra[w8] = s; rb[w8] = s2; }
    __syncthreads();
    if (threadIdx.x == 0) {
        s  = ra[0] + ra[1] + ra[2] + ra[3] + ra[4] + ra[5] + ra[6] + ra[7];
        s2 = rb[0] + rb[1] + rb[2] + rb[3] + rb[4] + rb[5] + rb[6] + rb[7];
        g_stats1[(n * C + c) * 2]     = s;
        g_stats1[(n * C + c) * 2 + 1] = s2;
    }
}

// ---------------- GN weight folding (both sets in one launch) ---------------
__global__ void __launch_bounds__(128) k_fold2(
    const float* __restrict__ W1, const float* __restrict__ g1c, const float* __restrict__ b1c,
    const float* __restrict__ W2, const float* __restrict__ g2c, const float* __restrict__ b2c)
{
    int id = blockIdx.x, t = threadIdx.x;
    int set = id >= C3;
    int m = set ? id - C3 : id;
    const float* W     = set ? W2 : W1;
    const float* gamma = set ? g2c : g1c;
    const float* beta  = set ? b2c : b1c;
    float* Wf = set ? g_Wf2 : g_Wf1;
    float* wb = set ? g_wb2 : g_wb1;
    float* wg = set ? g_wg2 : g_wg1;

    float sb = 0.f, sg = 0.f;
    for (int c = t; c < C; c += 128) {
        float wv = W[m * C + c];
        float gv = wv * gamma[c];
        Wf[m * C + c] = gv;
        sb += wv * beta[c];
        sg += gv;
    }
    __shared__ float a[4], g2[4];
    sb = warpsum(sb); sg = warpsum(sg);
    if ((t & 31) == 0) { a[t >> 5] = sb; g2[t >> 5] = sg; }
    __syncthreads();
    if (t == 0) {
        wb[m] = a[0] + a[1] + a[2] + a[3];
        wg[m] = g2[0] + g2[1] + g2[2] + g2[3];
    }
}

// ---------------- tf32 mma + cp.async helpers ------------------------------
__device__ __forceinline__ void mma_tf32(float c[4], const uint32_t a[4], const uint32_t b[2]) {
    asm volatile(
        "mma.sync.aligned.m16n8k8.row.col.f32.tf32.tf32.f32 "
        "{%0,%1,%2,%3}, {%4,%5,%6,%7}, {%8,%9}, {%0,%1,%2,%3};"
        : "+f"(c[0]), "+f"(c[1]), "+f"(c[2]), "+f"(c[3])
        : "r"(a[0]), "r"(a[1]), "r"(a[2]), "r"(a[3]), "r"(b[0]), "r"(b[1]));
}
__device__ __forceinline__ void cpa16(uint32_t s, const float* g) {
    asm volatile("cp.async.cg.shared.global [%0], [%1], 16;" :: "r"(s), "l"(g));
}

// ---------------- tf32 tensor-core GEMM, BK=32, 3-stage pipeline ------------
// EPI=0: C = alpha*acc
// EPI=1: C = acc + R[b] + bias[row]
// EPI=3: EPI=1 + write tile (sum,sumsq) to part[(b*nblk+blk)*2]
// EPI=2: GN fold; mean/istd from part (npart entries per sample);
//        C = istd*acc + (bias[row] - mean*istd*R[row])
#define STG 4608
template<int TRANSB, int EPI>
__global__ void __launch_bounds__(256) k_gemm_tc(
    const float* __restrict__ A, const float* __restrict__ B, float* __restrict__ Cm,
    int K, int lda, int ldb, int ldc,
    long sA, long sB, long sC,
    float alpha, const float* __restrict__ R, long sR, const float* __restrict__ bias,
    float* __restrict__ part, int npart)
{
    extern __shared__ float smem[];
    int b = blockIdx.z;
    const float* Ab = A + (size_t)b * sA;
    const float* Bb = B + (size_t)b * sB;
    int t = threadIdx.x;
    int rowBase = blockIdx.y * 128, colBase = blockIdx.x * 128;

    int ar = t >> 3, ac = (t & 7) << 2;
    int bk = t >> 5, bc = (t & 31) << 2;

    uint32_t asB = (uint32_t)__cvta_generic_to_shared(smem);
    uint32_t buB = (uint32_t)__cvta_generic_to_shared(smem + 3 * STG);

    auto loadStage = [&](int k0, int st) {
        #pragma unroll
        for (int r = 0; r < 4; r++) {
            int row = ar + r * 32;
            cpa16(asB + (uint32_t)(st * STG + row * KPAD + ac) * 4,
                  Ab + (size_t)(rowBase + row) * lda + k0 + ac);
        }
        if (TRANSB) {
            #pragma unroll
            for (int r = 0; r < 4; r++) {
                int row = ar + r * 32;
                cpa16(buB + (uint32_t)(st * STG + row * KPAD + ac) * 4,
                      Bb + (size_t)(colBase + row) * ldb + k0 + ac);
            }
        } else {
            #pragma unroll
            for (int r = 0; r < 4; r++) {
                int k = bk + r * 8;
                cpa16(buB + (uint32_t)(st * STG + k * 136 + bc) * 4,
                      Bb + (size_t)(k0 + k) * ldb + colBase + bc);
            }
        }
    };

    int nIter = K >> 5;
    loadStage(0, 0);
    asm volatile("cp.async.commit_group;");
    loadStage(32, 1);
    asm volatile("cp.async.commit_group;");

    int lane = t & 31, w = t >> 5;
    int wm = (w >> 2) * 64, wn = (w & 3) * 32;
    int lk = lane & 3, lm = lane >> 2;
    float acc[4][4][4] = {};

    int cur = 0;
    for (int it = 0; it < nIter; ++it) {
        if (it + 2 < nIter) { asm volatile("cp.async.wait_group 1;"); }
        else               { asm volatile("cp.async.wait_group 0;"); }
        __syncthreads();
        if (it + 2 < nIter) {
            int st = cur - 1; if (st < 0) st += 3;
            loadStage((it + 2) << 5, st);
            asm volatile("cp.async.commit_group;");
        }
        const float* Asc = smem + cur * STG;
        const float* Bsc = smem + 3 * STG + cur * STG;
        #pragma unroll
        for (int kk = 0; kk < 32; kk += 8) {
            uint32_t af[4][4], bf[4][2];
            #pragma unroll
            for (int mi = 0; mi < 4; mi++) {
                int row = wm + mi * 16 + lm;
                af[mi][0] = __float_as_uint(Asc[row * KPAD + kk + lk]);
                af[mi][1] = __float_as_uint(Asc[(row + 8) * KPAD + kk + lk]);
                af[mi][2] = __float_as_uint(Asc[row * KPAD + kk + 4 + lk]);
                af[mi][3] = __float_as_uint(Asc[(row + 8) * KPAD + kk + 4 + lk]);
            }
            #pragma unroll
            for (int ni = 0; ni < 4; ni++) {
                int col = wn + ni * 8 + lm;
                if (TRANSB) {
                    bf[ni][0] = __float_as_uint(Bsc[col * KPAD + kk + lk]);
                    bf[ni][1] = __float_as_uint(Bsc[col * KPAD + kk + 4 + lk]);
                } else {
                    bf[ni][0] = __float_as_uint(Bsc[(kk + lk) * 136 + col]);
                    bf[ni][1] = __float_as_uint(Bsc[(kk + 4 + lk) * 136 + col]);
                }
            }
            #pragma unroll
            for (int mi = 0; mi < 4; mi++)
                #pragma unroll
                for (int ni = 0; ni < 4; ni++)
                    mma_tf32(acc[mi][ni], af[mi], bf[ni]);
        }
        cur++; if (cur == 3) cur = 0;
    }

    float* Cb = Cm + (size_t)b * sC;
    const float* Rb = (EPI == 1 || EPI == 3) ? (R + (size_t)b * sR) : R;
    float mean = 0.f, istd = 1.f;
    if (EPI == 2) {
        __syncthreads();
        if (t < 32) {
            float s = 0.f, s2 = 0.f;
            for (int i = t; i < npart; i += 32) {
                s  += part[(b * npart + i) * 2];
                s2 += part[(b * npart + i) * 2 + 1];
            }
            s = warpsum(s); s2 = warpsum(s2);
            if (t == 0) { smem[0] = s; smem[1] = s2; }
        }
        __syncthreads();
        float invN = 1.f / (C * L);
        mean = smem[0] * invN;
        istd = rsqrtf(smem[1] * invN - mean * mean + EPS);
    }
    float ls = 0.f, ls2 = 0.f;
    #pragma unroll
    for (int mi = 0; mi < 4; mi++) {
        #pragma unroll
        for (int ni = 0; ni < 4; ni++) {
            int r0 = rowBase + wm + mi * 16 + lm;
            int cc = colBase + wn + ni * 8 + 2 * lk;
            if (EPI == 1 || EPI == 3) {
                float bv0 = bias[r0], bv1 = bias[r0 + 8];
                float2 rv0 = *(const float2*)(Rb + (size_t)r0 * ldc + cc);
                float2 rv1 = *(const float2*)(Rb + (size_t)(r0 + 8) * ldc + cc);
                float o0 = acc[mi][ni][0] + rv0.x + bv0;
                float o1 = acc[mi][ni][1] + rv0.y + bv0;
                float o2 = acc[mi][ni][2] + rv1.x + bv1;
                float o3 = acc[mi][ni][3] + rv1.y + bv1;
                *(float2*)(Cb + (size_t)r0 * ldc + cc)       = make_float2(o0, o1);
                *(float2*)(Cb + (size_t)(r0 + 8) * ldc + cc) = make_float2(o2, o3);
                if (EPI == 3) {
                    ls  += o0 + o1 + o2 + o3;
                    ls2 += o0 * o0 + o1 * o1 + o2 * o2 + o3 * o3;
                }
            } else if (EPI == 2) {
                float rb0 = bias[r0]     - mean * istd * Rb[r0];
                float rb1 = bias[r0 + 8] - mean * istd * Rb[r0 + 8];
                *(float2*)(Cb + (size_t)r0 * ldc + cc) =
                    make_float2(acc[mi][ni][0] * istd + rb0, acc[mi][ni][1] * istd + rb0);
                *(float2*)(Cb + (size_t)(r0 + 8) * ldc + cc) =
                    make_float2(acc[mi][ni][2] * istd + rb1, acc[mi][ni][3] * istd + rb1);
            } else {
                *(float2*)(Cb + (size_t)r0 * ldc + cc) =
                    make_float2(acc[mi][ni][0] * alpha, acc[mi][ni][1] * alpha);
                *(float2*)(Cb + (size_t)(r0 + 8) * ldc + cc) =
                    make_float2(acc[mi][ni][2] * alpha, acc[mi][ni][3] * alpha);
            }
        }
    }
    if (EPI == 3) {
        __syncthreads();
        ls = warpsum(ls); ls2 = warpsum(ls2);
        if (lane == 0) { smem[w * 2] = ls; smem[w * 2 + 1] = ls2; }
        __syncthreads();
        if (t == 0) {
            float s = 0.f, s2 = 0.f;
            #pragma unroll
            for (int i = 0; i < 8; i++) { s += smem[i * 2]; s2 += smem[i * 2 + 1]; }
            int nblk = gridDim.x * gridDim.y;
            int p = blockIdx.y * gridDim.x + blockIdx.x;
            part[(b * nblk + p) * 2]     = s;
            part[(b * nblk + p) * 2 + 1] = s2;
        }
    }
}

// ---------------- channel-attention softmax (rows of 384) ------------------
__global__ void __launch_bounds__(128) k_softmax(float* __restrict__ att) {
    float* p = att + (size_t)blockIdx.x * C;
    float v0 = p[threadIdx.x], v1 = p[threadIdx.x + 128], v2 = p[threadIdx.x + 256];
    float mx = fmaxf(v0, fmaxf(v1, v2));
    __shared__ float sh[4], sh2[4];
    #pragma unroll
    for (int o = 16; o; o >>= 1) mx = fmaxf(mx, __shfl_xor_sync(0xffffffffu, mx, o));
    if ((threadIdx.x & 31) == 0) sh[threadIdx.x >> 5] = mx;
    __syncthreads();
    mx = fmaxf(fmaxf(sh[0], sh[1]), fmaxf(sh[2], sh[3]));
    v0 = __expf(v0 - mx); v1 = __expf(v1 - mx); v2 = __expf(v2 - mx);
    float s = v0 + v1 + v2;
    #pragma unroll
    for (int o = 16; o; o >>= 1) s += __shfl_xor_sync(0xffffffffu, s, o);
    if ((threadIdx.x & 31) == 0) sh2[threadIdx.x >> 5] = s;
    __syncthreads();
    s = sh2[0] + sh2[1] + sh2[2] + sh2[3];
    float inv = 1.f / s;
    p[threadIdx.x] = v0 * inv; p[threadIdx.x + 128] = v1 * inv; p[threadIdx.x + 256] = v2 * inv;
}

// ---------------- spatial attention: flash-style tf32 MMA ------------------
__global__ void __launch_bounds__(256) k_spattn_mma() {
    extern __shared__ float sh[];
    float* KT  = sh;                       // [256][KPAD]
    float* VT  = sh + 256 * KPAD;          // [256][KPAD]
    float* Psm = sh + 2 * 256 * KPAD;      // 8 warps x [32][KPAD]
    int n = blockIdx.x / HEADS, h = blockIdx.x % HEADS;
    const float* base = g_qkv + (size_t)n * C3 * L + (size_t)h * (3 * HD) * L;
    int t = threadIdx.x, lane = t & 31, w = t >> 5;

    for (int i = t; i < HD * L; i += 256) {
        int d = i >> 8, l = i & 255;
        KT[l * KPAD + d] = base[(HD + d) * L + l];
        VT[l * KPAD + d] = base[(2 * HD + d) * L + l];
    }

    int lm = lane >> 2, lk = lane & 3;
    int qb = w * 32;
    const float scl = 0.17677669529663689f;
    uint32_t qf[2][4][4];
    #pragma unroll
    for (int mi = 0; mi < 2; mi++) {
        int r0 = qb + mi * 16 + lm;
        #pragma unroll
        for (int ks = 0; ks < 4; ks++) {
            int k0 = ks * 8;
            qf[mi][ks][0] = __float_as_uint(base[(k0 + lk) * L + r0]     * scl);
            qf[mi][ks][1] = __float_as_uint(base[(k0 + lk) * L + r0 + 8] * scl);
            qf[mi][ks][2] = __float_as_uint(base[(k0 + 4 + lk) * L + r0]     * scl);
            qf[mi][ks][3] = __float_as_uint(base[(k0 + 4 + lk) * L + r0 + 8] * scl);
        }
    }
    __syncthreads();

    float* Pw = Psm + w * 32 * KPAD;
    float m[4], lsum[4];
    #pragma unroll
    for (int i = 0; i < 4; i++) { m[i] = -1e30f; lsum[i] = 0.f; }
    float oacc[2][4][4] = {};

    for (int c0 = 0; c0 < L; c0 += 32) {
        float sacc[2][4][4] = {};
        #pragma unroll
        for (int ks = 0; ks < 4; ks++) {
            int kk = ks * 8;
            uint32_t bf[4][2];
            #pragma unroll
            for (int ni = 0; ni < 4; ni++) {
                int col = c0 + ni * 8 + lm;
                bf[ni][0] = __float_as_uint(KT[col * KPAD + kk + lk]);
                bf[ni][1] = __float_as_uint(KT[col * KPAD + kk + 4 + lk]);
            }
            #pragma unroll
            for (int mi = 0; mi < 2; mi++)
                #pragma unroll
                for (int ni = 0; ni < 4; ni++)
                    mma_tf32(sacc[mi][ni], qf[mi][ks], bf[ni]);
        }
        #pragma unroll
        for (int mi = 0; mi < 2; mi++) {
            float cm0 = -1e30f, cm1 = -1e30f;
            #pragma unroll
            for (int ni = 0; ni < 4; ni++) {
                cm0 = fmaxf(cm0, fmaxf(sacc[mi][ni][0], sacc[mi][ni][1]));
                cm1 = fmaxf(cm1, fmaxf(sacc[mi][ni][2], sacc[mi][ni][3]));
            }
            cm0 = fmaxf(cm0, __shfl_xor_sync(0xffffffffu, cm0, 1));
            cm0 = fmaxf(cm0, __shfl_xor_sync(0xffffffffu, cm0, 2));
            cm1 = fmaxf(cm1, __shfl_xor_sync(0xffffffffu, cm1, 1));
            cm1 = fmaxf(cm1, __shfl_xor_sync(0xffffffffu, cm1, 2));
            float nm0 = fmaxf(m[2 * mi],     cm0);
            float nm1 = fmaxf(m[2 * mi + 1], cm1);
            float f0 = __expf(m[2 * mi] - nm0);
            float f1 = __expf(m[2 * mi + 1] - nm1);
            float ps0 = 0.f, ps1 = 0.f;
            int rA = (mi * 16 + lm) * KPAD, rB = (mi * 16 + lm + 8) * KPAD;
            #pragma unroll
            for (int ni = 0; ni < 4; ni++) {
                float p0 = __expf(sacc[mi][ni][0] - nm0);
                float p1 = __expf(sacc[mi][ni][1] - nm0);
                float p2 = __expf(sacc[mi][ni][2] - nm1);
                float p3 = __expf(sacc[mi][ni][3] - nm1);
                ps0 += p0 + p1; ps1 += p2 + p3;
                int col = ni * 8 + 2 * lk;
                Pw[rA + col] = p0; Pw[rA + col + 1] = p1;
                Pw[rB + col] = p2; Pw[rB + col + 1] = p3;
            }
            ps0 += __shfl_xor_sync(0xffffffffu, ps0, 1);
            ps0 += __shfl_xor_sync(0xffffffffu, ps0, 2);
            ps1 += __shfl_xor_sync(0xffffffffu, ps1, 1);
            ps1 += __shfl_xor_sync(0xffffffffu, ps1, 2);
            lsum[2 * mi]     = lsum[2 * mi]     * f0 + ps0;
            lsum[2 * mi + 1] = lsum[2 * mi + 1] * f1 + ps1;
            #pragma unroll
            for (int ni = 0; ni < 4; ni++) {
                oacc[mi][ni][0] *= f0; oacc[mi][ni][1] *= f0;
                oacc[mi][ni][2] *= f1; oacc[mi][ni][3] *= f1;
            }
            m[2 * mi] = nm0; m[2 * mi + 1] = nm1;
        }
        __syncwarp();
        #pragma unroll
        for (int ks = 0; ks < 4; ks++) {
            int kk = ks * 8;
            uint32_t af[2][4], bf[4][2];
            #pragma unroll
            for (int mi = 0; mi < 2; mi++) {
                int row = mi * 16 + lm;
                af[mi][0] = __float_as_uint(Pw[row * KPAD + kk + lk]);
                af[mi][1] = __float_as_uint(Pw[(row + 8) * KPAD + kk + lk]);
                af[mi][2] = __float_as_uint(Pw[row * KPAD + kk + 4 + lk]);
                af[mi][3] = __float_as_uint(Pw[(row + 8) * KPAD + kk + 4 + lk]);
            }
            #pragma unroll
            for (int ni = 0; ni < 4; ni++) {
                int dcol = ni * 8 + lm;
                bf[ni][0] = __float_as_uint(VT[(c0 + kk + lk) * KPAD + dcol]);
                bf[ni][1] = __float_as_uint(VT[(c0 + kk + 4 + lk) * KPAD + dcol]);
            }
            #pragma unroll
            for (int mi = 0; mi < 2; mi++)
                #pragma unroll
                for (int ni = 0; ni < 4; ni++)
                    mma_tf32(oacc[mi][ni], af[mi], bf[ni]);
        }
        __syncwarp();
    }

    float inv[4];
    #pragma unroll
    for (int i = 0; i < 4; i++) inv[i] = 1.f / lsum[i];
    float* outp = g_vals + (size_t)n * C * L + (size_t)h * HD * L;
    #pragma unroll
    for (int mi = 0; mi < 2; mi++) {
        int r0 = qb + mi * 16 + lm;
        #pragma unroll
        for (int ni = 0; ni < 4; ni++) {
            int cc = ni * 8 + 2 * lk;
            outp[cc * L + r0]           = oacc[mi][ni][0] * inv[2 * mi];
            outp[(cc + 1) * L + r0]     = oacc[mi][ni][1] * inv[2 * mi];
            outp[cc * L + r0 + 8]       = oacc[mi][ni][2] * inv[2 * mi + 1];
            outp[(cc + 1) * L + r0 + 8] = oacc[mi][ni][3] * inv[2 * mi + 1];
        }
    }
}

// ---------------- depthwise convtranspose (k=8,s=4,p=2) + residual ---------
__global__ void __launch_bounds__(256) k_up(
    const float* __restrict__ x, const float* __restrict__ w,
    const float* __restrict__ ub, float* __restrict__ out)
{
    int idx = blockIdx.x * 256 + threadIdx.x;
    int xb = idx & 15;
    int yq = (idx >> 4) & 63;
    int c  = (idx >> 10) % C;
    int n  = idx / (1024 * C);
    const float* xdp = g_xd + ((size_t)n * C + c) * L;
    const float* wp  = w + c * 64;
    int iy1 = (yq + 2) >> 2;
    float res[4] = {0.f, 0.f, 0.f, 0.f};
    #pragma unroll
    for (int a = 0; a < 2; a++) {
        int iy = iy1 - a, ky = yq + 2 - 4 * iy;
        if ((unsigned)iy < 16u && (unsigned)ky < 8u) {
            const float* xr = xdp + iy * HH;
            float xm1 = (xb > 0)  ? xr[xb - 1] : 0.f;
            float x0  = xr[xb];
            float xp1 = (xb < 15) ? xr[xb + 1] : 0.f;
            const float* wr = wp + ky * 8;
            res[0] += x0 * wr[2];
            if (xb > 0)  res[0] += xm1 * wr[6];
            res[1] += x0 * wr[3];
            if (xb > 0)  res[1] += xm1 * wr[7];
            res[2] += x0 * wr[4];
            if (xb < 15) res[2] += xp1 * wr[0];
            res[3] += x0 * wr[5];
            if (xb < 15) res[3] += xp1 * wr[1];
        }
    }
    float4 xv = ((const float4*)x)[idx];
    float ubc = ub[c];
    ((float4*)out)[idx] = make_float4(xv.x + res[0] + ubc, xv.y + res[1] + ubc,
                                      xv.z + res[2] + ubc, xv.w + res[3] + ubc);
}

// ---------------- host launcher -------------------------------------------
#define GEMM_SMEM (6 * STG * 4)
#define SPATTN_SMEM ((2 * 256 * KPAD + 8 * 32 * KPAD) * 4)

extern "C" void kernel_launch(void* const* d_in, const int* in_sizes, int n_in,
                              void* d_out, int out_size)
{
    const float* x        = (const float*)d_in[0];
    const float* dw_w     = (const float*)d_in[1];
    const float* bn_gamma = (const float*)d_in[2];
    const float* bn_beta  = (const float*)d_in[3];
    const float* bn_mean  = (const float*)d_in[4];
    const float* bn_var   = (const float*)d_in[5];
    const float* lnch_g   = (const float*)d_in[6];
    const float* lnch_b   = (const float*)d_in[7];
    const float* pw_ch    = (const float*)d_in[8];
    const float* outch_w  = (const float*)d_in[9];
    const float* outch_b  = (const float*)d_in[10];
    const float* lnsp_g   = (const float*)d_in[11];
    const float* lnsp_b   = (const float*)d_in[12];
    const float* pw_sp    = (const float*)d_in[13];
    const float* outsp_w  = (const float*)d_in[14];
    const float* outsp_b  = (const float*)d_in[15];
    const float* up_w     = (const float*)d_in[16];
    const float* up_b     = (const float*)d_in[17];
    float* out = (float*)d_out;

    float *xd, *xd2, *qkv, *att, *vals, *st1, *st2;
    float *Wf1, *Wf2, *wb1, *wg1, *wb2, *wg2;
    cudaGetSymbolAddress((void**)&xd,   g_xd);
    cudaGetSymbolAddress((void**)&xd2,  g_xd2);
    cudaGetSymbolAddress((void**)&qkv,  g_qkv);
    cudaGetSymbolAddress((void**)&att,  g_att);
    cudaGetSymbolAddress((void**)&vals, g_vals);
    cudaGetSymbolAddress((void**)&st1,  g_stats1);
    cudaGetSymbolAddress((void**)&st2,  g_stats2);
    cudaGetSymbolAddress((void**)&Wf1,  g_Wf1);
    cudaGetSymbolAddress((void**)&Wf2,  g_Wf2);
    cudaGetSymbolAddress((void**)&wb1,  g_wb1);
    cudaGetSymbolAddress((void**)&wg1,  g_wg1);
    cudaGetSymbolAddress((void**)&wb2,  g_wb2);
    cudaGetSymbolAddress((void**)&wg2,  g_wg2);

    cudaFuncSetAttribute(k_gemm_tc<0, 0>, cudaFuncAttributeMaxDynamicSharedMemorySize, GEMM_SMEM);
    cudaFuncSetAttribute(k_gemm_tc<1, 0>, cudaFuncAttributeMaxDynamicSharedMemorySize, GEMM_SMEM);
    cudaFuncSetAttribute(k_gemm_tc<0, 1>, cudaFuncAttributeMaxDynamicSharedMemorySize, GEMM_SMEM);
    cudaFuncSetAttribute(k_gemm_tc<0, 2>, cudaFuncAttributeMaxDynamicSharedMemorySize, GEMM_SMEM);
    cudaFuncSetAttribute(k_gemm_tc<0, 3>, cudaFuncAttributeMaxDynamicSharedMemorySize, GEMM_SMEM);
    cudaFuncSetAttribute(k_spattn_mma, cudaFuncAttributeMaxDynamicSharedMemorySize, SPATTN_SMEM);

    // 0) fold GN affine params into projection weights (both sets, one launch)
    k_fold2<<<2 * C3, 128>>>(pw_ch, lnch_g, lnch_b, pw_sp, lnsp_g, lnsp_b);

    // 1) downsample conv + BN + fused GN#1 partial stats -> g_stats1
    k_dwconv<<<NB * C, 256>>>(x, dw_w, bn_gamma, bn_beta, bn_mean, bn_var);

    // 2) qkv[n] = GN-folded QKV #1 (EPI=2, stats from g_stats1, npart=C)
    k_gemm_tc<0, 2><<<dim3(L / 128, C3 / 128, NB), 256, GEMM_SMEM>>>(
        Wf1, xd, qkv, C, C, L, L,
        0, (long)C * L, (long)C3 * L, 1.f, wg1, 0, wb1, st1, C);

    // 3) scores[n] = q[n] @ k[n]^T / 16
    k_gemm_tc<1, 0><<<dim3(C / 128, C / 128, NB), 256, GEMM_SMEM>>>(
        qkv, qkv + (size_t)C * L, att, L, L, L, C,
        (long)C3 * L, (long)C3 * L, (long)C * C,
        1.f / 16.f, nullptr, 0, nullptr, nullptr, 0);

    // 4) softmax rows
    k_softmax<<<NB * C, 128>>>(att);

    // 5) vals[n] = att[n] @ v[n]
    k_gemm_tc<0, 0><<<dim3(L / 128, C / 128, NB), 256, GEMM_SMEM>>>(
        att, qkv + (size_t)2 * C * L, vals, C, C, L, L,
        (long)C * C, (long)C3 * L, (long)C * L,
        1.f, nullptr, 0, nullptr, nullptr, 0);

    // 6) xd2[n] = outch_w @ vals[n] + xd[n] + outch_b, + GN#2 partials (EPI=3)
    k_gemm_tc<0, 3><<<dim3(L / 128, C / 128, NB), 256, GEMM_SMEM>>>(
        outch_w, vals, xd2, C, C, L, L,
        0, (long)C * L, (long)C * L,
        1.f, xd, (long)C * L, outch_b, st2, 0);

    // 7) qkv[n] = GN-folded QKV #2 (EPI=2, stats from g_stats2, npart=6)
    k_gemm_tc<0, 2><<<dim3(L / 128, C3 / 128, NB), 256, GEMM_SMEM>>>(
        Wf2, xd2, qkv, C, C, L, L,
        0, (long)C * L, (long)C3 * L, 1.f, wg2, 0, wb2, st2, 6);

    // 8) fused spatial attention (tensor-core flash)
    k_spattn_mma<<<NB * HEADS, 256, SPATTN_SMEM>>>();

    // 9) xd[n] = outsp_w @ vals[n] + xd2[n] + outsp_b
    k_gemm_tc<0, 1><<<dim3(L / 128, C / 128, NB), 256, GEMM_SMEM>>>(
        outsp_w, vals, xd, C, C, L, L,
        0, (long)C * L, (long)C * L,
        1.f, xd2, (long)C * L, outsp_b, nullptr, 0);

    // 10) upsample transposed conv + residual
    k_up<<<(NB * C * HIN * HIN / 4) / 256, 256>>>(x, up_w, up_b, out);
}